// round 5
// baseline (speedup 1.0000x reference)
#include <cuda_runtime.h>

#define BB 32
#define CC 512
#define HC 128
#define HW 4096
#define EPS_BN 0.001f

// scratch (no allocations allowed anywhere); zero-initialized at module load
__device__ float g_s[BB * CC];        // pooled means [B, C]
__device__ float g_es[BB * CC];       // e * scale2   [B, C]
__device__ float g_shift[CC];         // shift2       [C]
__device__ unsigned g_cnt[BB];        // reduce-completion counters
__device__ int g_flag[BB];            // excitation-ready flags
__device__ unsigned g_done[BB];       // scale-completion counters (for self-reset)

// ---------------------------------------------------------------------------
// Single fused kernel. One block per (b,c) plane:
//   1) load plane into registers (16 floats/thread), compute mean
//   2) last block of each batch computes the excitation MLP (coalesced)
//   3) all blocks wait for their batch flag, then write y from registers
// ---------------------------------------------------------------------------
__global__ void __launch_bounds__(256, 6) se_fused(
    const float* __restrict__ x, float* __restrict__ y,
    const float* __restrict__ w1, const float* __restrict__ g1,
    const float* __restrict__ b1, const float* __restrict__ m1,
    const float* __restrict__ v1, const float* __restrict__ w2,
    const float* __restrict__ g2, const float* __restrict__ b2,
    const float* __restrict__ m2, const float* __restrict__ v2) {

    const int plane = blockIdx.x;          // b*CC + c
    const int batch = plane >> 9;
    const int chan  = plane & (CC - 1);
    const int tid   = threadIdx.x;
    const int wid   = tid >> 5;
    const int lane  = tid & 31;

    // ---- load plane into registers (streaming: no reuse after this kernel)
    const float4* xp = reinterpret_cast<const float4*>(x) +
                       (size_t)plane * (HW / 4) + tid;
    float4 v[4];
#pragma unroll
    for (int i = 0; i < 4; i++) v[i] = __ldcs(xp + i * 256);

    // ---- per-plane mean
    float sum = 0.f;
#pragma unroll
    for (int i = 0; i < 4; i++) sum += (v[i].x + v[i].y) + (v[i].z + v[i].w);
#pragma unroll
    for (int o = 16; o > 0; o >>= 1)
        sum += __shfl_down_sync(0xffffffffu, sum, o);

    __shared__ float red[8];
    __shared__ int s_last;
    if (lane == 0) red[wid] = sum;
    __syncthreads();
    if (tid == 0) {
        float s = 0.f;
#pragma unroll
        for (int i = 0; i < 8; i++) s += red[i];
        g_s[plane] = s * (1.0f / HW);
        __threadfence();                              // release mean
        unsigned old = atomicAdd(&g_cnt[batch], 1u);
        s_last = (old == CC - 1);
    }
    __syncthreads();

    // ---- the block that completed this batch computes the excitation MLP
    if (s_last) {
        __threadfence();                              // acquire peers' means
        __shared__ float s_s[CC];
        __shared__ float s_h[HC];
        for (int i = tid; i < CC; i += 256) s_s[i] = __ldcg(&g_s[batch * CC + i]);
        __syncthreads();

        // h[j]: 8 warps x 16 rows, coalesced weight reads + shfl reduce
#pragma unroll 2
        for (int r = 0; r < 16; r++) {
            const int j = wid * 16 + r;
            const float* wr = w1 + j * CC;
            float acc = 0.f;
#pragma unroll
            for (int i = 0; i < CC / 32; i++)
                acc = fmaf(wr[lane + 32 * i], s_s[lane + 32 * i], acc);
#pragma unroll
            for (int o = 16; o > 0; o >>= 1)
                acc += __shfl_down_sync(0xffffffffu, acc, o);
            if (lane == 0) {
                float hv = (acc - m1[j]) * (g1[j] * rsqrtf(v1[j] + EPS_BN)) + b1[j];
                s_h[j] = fmaxf(hv, 0.f);
            }
        }
        __syncthreads();

        // e[c]*scale2: 8 warps x 64 rows
#pragma unroll 2
        for (int r = 0; r < 64; r++) {
            const int c = wid * 64 + r;
            const float* wr = w2 + c * HC;
            float acc = 0.f;
#pragma unroll
            for (int i = 0; i < HC / 32; i++)
                acc = fmaf(wr[lane + 32 * i], s_h[lane + 32 * i], acc);
#pragma unroll
            for (int o = 16; o > 0; o >>= 1)
                acc += __shfl_down_sync(0xffffffffu, acc, o);
            if (lane == 0) {
                const float sc2 = g2[c] * rsqrtf(v2[c] + EPS_BN);
                g_es[batch * CC + c] = acc * sc2;
                g_shift[c] = fmaf(-m2[c], sc2, b2[c]);  // same value each batch
            }
        }
        __syncthreads();
        if (tid == 0) {
            __threadfence();                           // release es/shift
            *(volatile int*)&g_flag[batch] = 1;
        }
    }

    // ---- wait for this batch's excitation, then scale from registers
    __shared__ float sh_es, sh_shift;
    if (tid == 0) {
        while (*(volatile int*)&g_flag[batch] == 0) __nanosleep(64);
        __threadfence();                               // acquire es/shift
        sh_es    = __ldcg(&g_es[plane]);
        sh_shift = __ldcg(&g_shift[chan]);
    }
    __syncthreads();
    const float es = sh_es, shift = sh_shift;

    float4* yp = reinterpret_cast<float4*>(y) + (size_t)plane * (HW / 4) + tid;
#pragma unroll
    for (int i = 0; i < 4; i++) {
        float4 o;
        o.x = fmaf(v[i].x, es, shift);
        o.y = fmaf(v[i].y, es, shift);
        o.z = fmaf(v[i].z, es, shift);
        o.w = fmaf(v[i].w, es, shift);
        __stcs(yp + i * 256, o);
    }

    // ---- self-reset for graph replay: last block to finish its batch cleans up
    if (tid == 0) {
        unsigned d = atomicAdd(&g_done[batch], 1u);
        if (d == CC - 1) {
            g_cnt[batch]  = 0;
            g_done[batch] = 0;
            *(volatile int*)&g_flag[batch] = 0;
        }
    }
}

// ---------------------------------------------------------------------------
extern "C" void kernel_launch(void* const* d_in, const int* in_sizes, int n_in,
                              void* d_out, int out_size) {
    const float* x  = (const float*)d_in[0];
    const float* w1 = (const float*)d_in[1];
    const float* g1 = (const float*)d_in[2];
    const float* b1 = (const float*)d_in[3];
    const float* m1 = (const float*)d_in[4];
    const float* v1 = (const float*)d_in[5];
    const float* w2 = (const float*)d_in[6];
    const float* g2 = (const float*)d_in[7];
    const float* b2 = (const float*)d_in[8];
    const float* m2 = (const float*)d_in[9];
    const float* v2 = (const float*)d_in[10];
    float* y = (float*)d_out;

    se_fused<<<BB * CC, 256>>>(x, y, w1, g1, b1, m1, v1, w2, g2, b2, m2, v2);
}

// round 6
// speedup vs baseline: 2.6859x; 2.6859x over previous
#include <cuda_runtime.h>

#define BB 32
#define CC 512
#define HC 128
#define HW 4096
#define GROUP 8            // 8 batches * 512 planes * 16KB = 67MB < 126MB L2
#define NGROUP (BB / GROUP)
#define EPS_BN 0.001f

// scratch (no device allocations allowed anywhere)
__device__ float g_s[BB * CC];      // pooled means [B, C]
__device__ float g_es[BB * CC];     // e * scale2   [B, C]
__device__ float g_shift[CC];       // shift2       [C]

// ---------------------------------------------------------------------------
// Kernel 1: per-plane mean for one group (default caching -> x lands in L2).
// ---------------------------------------------------------------------------
__global__ void __launch_bounds__(256) se_reduce(const float* __restrict__ x,
                                                 int base_batch) {
    const int plane = base_batch * CC + blockIdx.x;
    const float4* xp = reinterpret_cast<const float4*>(x + (size_t)plane * HW);

    float sum = 0.f;
#pragma unroll
    for (int i = 0; i < HW / 4 / 256; i++) {
        float4 v = xp[i * 256 + threadIdx.x];
        sum += (v.x + v.y) + (v.z + v.w);
    }
#pragma unroll
    for (int o = 16; o > 0; o >>= 1)
        sum += __shfl_down_sync(0xffffffffu, sum, o);

    __shared__ float red[8];
    if ((threadIdx.x & 31) == 0) red[threadIdx.x >> 5] = sum;
    __syncthreads();
    if (threadIdx.x == 0) {
        float s = 0.f;
#pragma unroll
        for (int i = 0; i < 8; i++) s += red[i];
        g_s[plane] = s * (1.0f / HW);
    }
}

// ---------------------------------------------------------------------------
// Kernel 2: excitation MLP for one group. One block per batch; warp-
// cooperative (coalesced) dot products.
// ---------------------------------------------------------------------------
__global__ void __launch_bounds__(256) se_excite(
    int base_batch,
    const float* __restrict__ w1, const float* __restrict__ g1,
    const float* __restrict__ b1, const float* __restrict__ m1,
    const float* __restrict__ v1, const float* __restrict__ w2,
    const float* __restrict__ g2, const float* __restrict__ b2,
    const float* __restrict__ m2, const float* __restrict__ v2) {
    __shared__ float s_s[CC];
    __shared__ float s_h[HC];

    const int b    = base_batch + blockIdx.x;
    const int wid  = threadIdx.x >> 5;
    const int lane = threadIdx.x & 31;

    for (int i = threadIdx.x; i < CC; i += 256) s_s[i] = g_s[b * CC + i];
    __syncthreads();

#pragma unroll 2
    for (int r = 0; r < 16; r++) {
        const int j = wid * 16 + r;
        const float* wr = w1 + j * CC;
        float acc = 0.f;
#pragma unroll
        for (int i = 0; i < CC / 32; i++)
            acc = fmaf(wr[lane + 32 * i], s_s[lane + 32 * i], acc);
#pragma unroll
        for (int o = 16; o > 0; o >>= 1)
            acc += __shfl_down_sync(0xffffffffu, acc, o);
        if (lane == 0) {
            float hv = (acc - m1[j]) * (g1[j] * rsqrtf(v1[j] + EPS_BN)) + b1[j];
            s_h[j] = fmaxf(hv, 0.f);
        }
    }
    __syncthreads();

#pragma unroll 2
    for (int r = 0; r < 64; r++) {
        const int c = wid * 64 + r;
        const float* wr = w2 + c * HC;
        float acc = 0.f;
#pragma unroll
        for (int i = 0; i < HC / 32; i++)
            acc = fmaf(wr[lane + 32 * i], s_h[lane + 32 * i], acc);
#pragma unroll
        for (int o = 16; o > 0; o >>= 1)
            acc += __shfl_down_sync(0xffffffffu, acc, o);
        if (lane == 0) {
            const float sc2 = g2[c] * rsqrtf(v2[c] + EPS_BN);
            g_es[b * CC + c] = acc * sc2;
            if (blockIdx.x == 0) g_shift[c] = fmaf(-m2[c], sc2, b2[c]);
        }
    }
}

// ---------------------------------------------------------------------------
// Kernel 3: y = x*es + shift for one group. x reads should hit L2 (streamed
// in by this group's reduce); y stores evict-first.
// ---------------------------------------------------------------------------
__global__ void __launch_bounds__(256) se_scale(const float* __restrict__ x,
                                                float* __restrict__ y,
                                                int base_batch) {
    const int plane = base_batch * CC + blockIdx.x;
    const float es    = g_es[plane];
    const float shift = g_shift[plane & (CC - 1)];

    const size_t base = (size_t)plane * (HW / 4);
    const float4* xp = reinterpret_cast<const float4*>(x) + base + threadIdx.x;
    float4*       yp = reinterpret_cast<float4*>(y) + base + threadIdx.x;

    float4 v0 = __ldcg(xp + 0 * 256);
    float4 v1 = __ldcg(xp + 1 * 256);
    float4 v2 = __ldcg(xp + 2 * 256);
    float4 v3 = __ldcg(xp + 3 * 256);

    float4 o0, o1, o2, o3;
    o0.x = fmaf(v0.x, es, shift); o0.y = fmaf(v0.y, es, shift);
    o0.z = fmaf(v0.z, es, shift); o0.w = fmaf(v0.w, es, shift);
    o1.x = fmaf(v1.x, es, shift); o1.y = fmaf(v1.y, es, shift);
    o1.z = fmaf(v1.z, es, shift); o1.w = fmaf(v1.w, es, shift);
    o2.x = fmaf(v2.x, es, shift); o2.y = fmaf(v2.y, es, shift);
    o2.z = fmaf(v2.z, es, shift); o2.w = fmaf(v2.w, es, shift);
    o3.x = fmaf(v3.x, es, shift); o3.y = fmaf(v3.y, es, shift);
    o3.z = fmaf(v3.z, es, shift); o3.w = fmaf(v3.w, es, shift);

    __stcs(yp + 0 * 256, o0);
    __stcs(yp + 1 * 256, o1);
    __stcs(yp + 2 * 256, o2);
    __stcs(yp + 3 * 256, o3);
}

// ---------------------------------------------------------------------------
// Pipelined launch: reduces+excites serialized on the caller's stream,
// scales on a side stream gated per-group by events, so scale_g overlaps
// reduce_{g+1}. Streams/events created lazily on the first (non-capture)
// call; fork/join via events is graph-capturable.
// ---------------------------------------------------------------------------
extern "C" void kernel_launch(void* const* d_in, const int* in_sizes, int n_in,
                              void* d_out, int out_size) {
    const float* x  = (const float*)d_in[0];
    const float* w1 = (const float*)d_in[1];
    const float* g1 = (const float*)d_in[2];
    const float* b1 = (const float*)d_in[3];
    const float* m1 = (const float*)d_in[4];
    const float* v1 = (const float*)d_in[5];
    const float* w2 = (const float*)d_in[6];
    const float* g2 = (const float*)d_in[7];
    const float* b2 = (const float*)d_in[8];
    const float* m2 = (const float*)d_in[9];
    const float* v2 = (const float*)d_in[10];
    float* y = (float*)d_out;

    static cudaStream_t side = nullptr;
    static cudaEvent_t  ev_ready[NGROUP];
    static cudaEvent_t  ev_join;
    if (side == nullptr) {
        cudaStreamCreateWithFlags(&side, cudaStreamNonBlocking);
        for (int g = 0; g < NGROUP; g++)
            cudaEventCreateWithFlags(&ev_ready[g], cudaEventDisableTiming);
        cudaEventCreateWithFlags(&ev_join, cudaEventDisableTiming);
    }

    for (int g = 0; g < NGROUP; g++) {
        const int base = g * GROUP;
        se_reduce<<<GROUP * CC, 256>>>(x, base);
        se_excite<<<GROUP, 256>>>(base, w1, g1, b1, m1, v1,
                                  w2, g2, b2, m2, v2);
        cudaEventRecord(ev_ready[g], 0);
        cudaStreamWaitEvent(side, ev_ready[g], 0);
        se_scale<<<GROUP * CC, 256, 0, side>>>(x, y, base);
    }
    // join the side stream back into the caller's stream
    cudaEventRecord(ev_join, side);
    cudaStreamWaitEvent(0, ev_join, 0);
}

// round 7
// speedup vs baseline: 5.5619x; 2.0708x over previous
#include <cuda_runtime.h>

#define BB 32
#define CC 512
#define HC 128
#define HW 4096
#define NPLANE (BB * CC)
#define EPS_BN 0.001f

// scratch (no device allocations allowed anywhere)
__device__ float g_s[BB * CC];      // pooled means [B, C]
__device__ float g_es[BB * CC];     // e * scale2   [B, C]
__device__ float g_shift[CC];       // shift2       [C]

// ---------------------------------------------------------------------------
// Kernel 1: per-plane mean, full grid. Default caching -> x streams through
// L2 and the tail (~126MB, highest planes) stays resident for kernel 3.
// ---------------------------------------------------------------------------
__global__ void __launch_bounds__(256) se_reduce(const float* __restrict__ x) {
    const int plane = blockIdx.x;
    const float4* xp = reinterpret_cast<const float4*>(x + (size_t)plane * HW);

    float sum = 0.f;
#pragma unroll
    for (int i = 0; i < HW / 4 / 256; i++) {
        float4 v = xp[i * 256 + threadIdx.x];
        sum += (v.x + v.y) + (v.z + v.w);
    }
#pragma unroll
    for (int o = 16; o > 0; o >>= 1)
        sum += __shfl_down_sync(0xffffffffu, sum, o);

    __shared__ float red[8];
    if ((threadIdx.x & 31) == 0) red[threadIdx.x >> 5] = sum;
    __syncthreads();
    if (threadIdx.x == 0) {
        float s = 0.f;
#pragma unroll
        for (int i = 0; i < 8; i++) s += red[i];
        g_s[plane] = s * (1.0f / HW);
    }
}

// ---------------------------------------------------------------------------
// Kernel 2: excitation MLP, one block per batch (32 blocks). Warp-cooperative
// coalesced dot products.
// ---------------------------------------------------------------------------
__global__ void __launch_bounds__(256) se_excite(
    const float* __restrict__ w1, const float* __restrict__ g1,
    const float* __restrict__ b1, const float* __restrict__ m1,
    const float* __restrict__ v1, const float* __restrict__ w2,
    const float* __restrict__ g2, const float* __restrict__ b2,
    const float* __restrict__ m2, const float* __restrict__ v2) {
    __shared__ float s_s[CC];
    __shared__ float s_h[HC];

    const int b    = blockIdx.x;
    const int wid  = threadIdx.x >> 5;
    const int lane = threadIdx.x & 31;

    for (int i = threadIdx.x; i < CC; i += 256) s_s[i] = g_s[b * CC + i];
    __syncthreads();

#pragma unroll 2
    for (int r = 0; r < 16; r++) {
        const int j = wid * 16 + r;
        const float* wr = w1 + j * CC;
        float acc = 0.f;
#pragma unroll
        for (int i = 0; i < CC / 32; i++)
            acc = fmaf(wr[lane + 32 * i], s_s[lane + 32 * i], acc);
#pragma unroll
        for (int o = 16; o > 0; o >>= 1)
            acc += __shfl_down_sync(0xffffffffu, acc, o);
        if (lane == 0) {
            float hv = (acc - m1[j]) * (g1[j] * rsqrtf(v1[j] + EPS_BN)) + b1[j];
            s_h[j] = fmaxf(hv, 0.f);
        }
    }
    __syncthreads();

#pragma unroll 2
    for (int r = 0; r < 64; r++) {
        const int c = wid * 64 + r;
        const float* wr = w2 + c * HC;
        float acc = 0.f;
#pragma unroll
        for (int i = 0; i < HC / 32; i++)
            acc = fmaf(wr[lane + 32 * i], s_h[lane + 32 * i], acc);
#pragma unroll
        for (int o = 16; o > 0; o >>= 1)
            acc += __shfl_down_sync(0xffffffffu, acc, o);
        if (lane == 0) {
            const float sc2 = g2[c] * rsqrtf(v2[c] + EPS_BN);
            g_es[b * CC + c] = acc * sc2;
            if (b == 0) g_shift[c] = fmaf(-m2[c], sc2, b2[c]);
        }
    }
}

// ---------------------------------------------------------------------------
// Kernel 3: y = x*es + shift, full grid, REVERSED plane order so the first
// waves read the x tail that kernel 1 left in L2. 2 planes per block,
// 8 front-batched ldcg loads (MLP=8), evict-first stores.
// ---------------------------------------------------------------------------
__global__ void __launch_bounds__(256) se_scale(const float* __restrict__ x,
                                                float* __restrict__ y) {
    // reversed: block 0 handles the last 2 planes (freshest in L2)
    const int plane0 = NPLANE - 2 - blockIdx.x * 2;

    float es[2], sh[2];
#pragma unroll
    for (int p = 0; p < 2; p++) {
        es[p] = g_es[plane0 + p];
        sh[p] = g_shift[(plane0 + p) & (CC - 1)];
    }

    const size_t base = (size_t)plane0 * (HW / 4);
    const float4* xp = reinterpret_cast<const float4*>(x) + base + threadIdx.x;
    float4*       yp = reinterpret_cast<float4*>(y) + base + threadIdx.x;

    float4 v[8];
#pragma unroll
    for (int i = 0; i < 8; i++) v[i] = __ldcg(xp + i * 256);

#pragma unroll
    for (int i = 0; i < 8; i++) {
        const float e = es[i >> 2], s = sh[i >> 2];
        float4 o;
        o.x = fmaf(v[i].x, e, s);
        o.y = fmaf(v[i].y, e, s);
        o.z = fmaf(v[i].z, e, s);
        o.w = fmaf(v[i].w, e, s);
        __stcs(yp + i * 256, o);
    }
}

// ---------------------------------------------------------------------------
extern "C" void kernel_launch(void* const* d_in, const int* in_sizes, int n_in,
                              void* d_out, int out_size) {
    const float* x  = (const float*)d_in[0];
    const float* w1 = (const float*)d_in[1];
    const float* g1 = (const float*)d_in[2];
    const float* b1 = (const float*)d_in[3];
    const float* m1 = (const float*)d_in[4];
    const float* v1 = (const float*)d_in[5];
    const float* w2 = (const float*)d_in[6];
    const float* g2 = (const float*)d_in[7];
    const float* b2 = (const float*)d_in[8];
    const float* m2 = (const float*)d_in[9];
    const float* v2 = (const float*)d_in[10];
    float* y = (float*)d_out;

    se_reduce<<<NPLANE, 256>>>(x);
    se_excite<<<BB, 256>>>(w1, g1, b1, m1, v1, w2, g2, b2, m2, v2);
    se_scale<<<NPLANE / 2, 256>>>(x, y);
}